// round 14
// baseline (speedup 1.0000x reference)
#include <cuda_runtime.h>
#include <cuda_bf16.h>

#define NN 50000
#define EE 600000
#define HH 128
#define GG 2048
#define FIN 11
#define LL 5
#define EPSV 1e-5f
#define SCAN_B 49   // ceil(NN/1024)

// ---------------- scratch (static device globals) ----------------
__device__ float        g_dinv[NN];
__device__ int          g_cnt[NN];
__device__ int          g_off[NN + 1];
__device__ int          g_cur[NN];
__device__ int2         g_csr[EE];            // {src, nrm-bits}
__device__ unsigned int g_hb[NN * (HH / 2)];  // h  bf16x2, [N][64]
__device__ unsigned int g_xb[NN * (HH / 2)];  // x  bf16x2, [N][64]
__device__ int          g_start[GG + 1];
__device__ int          g_part[64];
// pre-split weights: [layer][k2 0..63][n 0..127], bf16x2 packed along k
__device__ unsigned int g_wh[(LL - 1) * 64 * HH];
__device__ unsigned int g_wl[(LL - 1) * 64 * HH];

// ---------------- bf16 helpers ----------------
__device__ __forceinline__ unsigned packbf2(float a, float b) {
    unsigned r;
    asm("cvt.rn.bf16x2.f32 %0, %1, %2;" : "=r"(r) : "f"(b), "f"(a));
    return r;  // low half = a, high half = b
}
__device__ __forceinline__ float bflo(unsigned w) { return __uint_as_float(w << 16); }
__device__ __forceinline__ float bfhi(unsigned w) { return __uint_as_float(w & 0xFFFF0000u); }

__device__ __forceinline__ void mma_bf16(float* d, const unsigned* a, const unsigned* b) {
    asm volatile(
        "mma.sync.aligned.m16n8k16.row.col.f32.bf16.bf16.f32 "
        "{%0,%1,%2,%3}, {%4,%5,%6,%7}, {%8,%9}, {%0,%1,%2,%3};"
        : "+f"(d[0]), "+f"(d[1]), "+f"(d[2]), "+f"(d[3])
        : "r"(a[0]), "r"(a[1]), "r"(a[2]), "r"(a[3]), "r"(b[0]), "r"(b[1]));
}

// ---------------- degree / CSR build ----------------
__global__ void k_zero_cnt() {
    int i = blockIdx.x * blockDim.x + threadIdx.x;
    if (i < NN) g_cnt[i] = 0;
}

__global__ void k_count(const int* __restrict__ ei) {
    int e = blockIdx.x * blockDim.x + threadIdx.x;
    if (e < EE) atomicAdd(&g_cnt[ei[EE + e]], 1);
}

// ---- coalesced 2-phase scan (phase 1 also computes dinv) ----
__global__ void k_scan1() {
    int t = threadIdx.x, b = blockIdx.x;
    int i = b * 1024 + t;
    int v = (i < NN) ? g_cnt[i] : 0;
    if (i < NN) g_dinv[i] = rsqrtf((float)v + 1.0f);   // +1 self-loop
    int lane = t & 31, wid = t >> 5;
    int x = v;
    #pragma unroll
    for (int d = 1; d < 32; d <<= 1) {
        int n = __shfl_up_sync(0xFFFFFFFF, x, d);
        if (lane >= d) x += n;
    }
    __shared__ int ws[32];
    if (lane == 31) ws[wid] = x;
    __syncthreads();
    if (wid == 0) {
        int w = ws[lane];
        #pragma unroll
        for (int d = 1; d < 32; d <<= 1) {
            int n = __shfl_up_sync(0xFFFFFFFF, w, d);
            if (lane >= d) w += n;
        }
        ws[lane] = w;
    }
    __syncthreads();
    int incl = x + (wid ? ws[wid - 1] : 0);
    if (i < NN) g_off[i] = incl - v;
    if (t == 1023) g_part[b] = incl;
}

// phase 2: redundant prefix of 49 partials + offsets + per-graph boundaries
__global__ void k_scan3(const int* __restrict__ batch) {
    __shared__ int ps[SCAN_B];
    int t = threadIdx.x;
    if (t == 0) {
        int run = 0;
        #pragma unroll
        for (int j = 0; j < SCAN_B; j++) {
            int v = g_part[j];
            ps[j] = run;
            run += v;
        }
        if (blockIdx.x == 0) g_off[NN] = run;
    }
    __syncthreads();
    int i = blockIdx.x * blockDim.x + t;
    if (i >= NN) return;
    int o = g_off[i] + ps[i >> 10];
    g_off[i] = o;
    g_cur[i] = o;
    int b = batch[i];
    if (i == 0) {
        for (int g = 0; g <= b; g++) g_start[g] = 0;
    } else {
        int pb = batch[i - 1];
        for (int g = pb + 1; g <= b; g++) g_start[g] = i;
    }
    if (i == NN - 1) {
        for (int g = b + 1; g <= GG; g++) g_start[g] = NN;
    }
}

__global__ void k_fill(const int* __restrict__ ei) {
    int e = blockIdx.x * blockDim.x + threadIdx.x;
    if (e < EE) {
        int s = ei[e];
        int d = ei[EE + e];
        int p = atomicAdd(&g_cur[d], 1);
        g_csr[p] = make_int2(s, __float_as_int(g_dinv[s] * g_dinv[d]));
    }
}

// ---------------- W pre-split: fp32 [L-1][128k][128n] -> bf16x2 hi/lo along k ------
__global__ void k_wsplit(const float* __restrict__ Ws) {
    int idx = blockIdx.x * blockDim.x + threadIdx.x;   // (l, k2, n)
    if (idx >= (LL - 1) * 64 * HH) return;
    int n = idx & 127;
    int k2 = (idx >> 7) & 63;
    int l = idx >> 13;
    const float* W = Ws + l * HH * HH;
    float w0 = W[(2 * k2) * HH + n];
    float w1 = W[(2 * k2 + 1) * HH + n];
    unsigned h = packbf2(w0, w1);
    float r0 = w0 - bflo(h);
    float r1 = w1 - bfhi(h);
    g_wh[idx] = h;
    g_wl[idx] = packbf2(r0, r1);
}

// ---------------- GEMM: layer 0 (K = 11), writes g_hb ----------------
__global__ void k_gemm0(const float* __restrict__ X, const float* __restrict__ W0) {
    __shared__ float sW[FIN * HH];
    __shared__ float sx[16 * FIN];
    int t = threadIdx.x;
    int rowBase = blockIdx.x * 16;
    for (int idx = t; idx < FIN * HH; idx += 256) sW[idx] = W0[idx];
    if (t < 16 * FIN) {
        int r = rowBase + t / FIN;
        sx[t] = (r < NN) ? X[r * FIN + (t % FIN)] : 0.0f;
    }
    __syncthreads();
    int c = t & 127;
    int rh = t >> 7;
    float w[FIN];
    #pragma unroll
    for (int k = 0; k < FIN; k++) w[k] = sW[k * HH + c];
    #pragma unroll
    for (int i = 0; i < 8; i++) {
        int rloc = rh + 2 * i;
        int r = rowBase + rloc;
        if (r < NN) {
            float acc = 0.0f;
            #pragma unroll
            for (int k = 0; k < FIN; k++) acc += sx[rloc * FIN + k] * w[k];
            float other = __shfl_xor_sync(0xFFFFFFFF, acc, 1);
            if ((c & 1) == 0)
                g_hb[r * 64 + (c >> 1)] = packbf2(acc, other);
        }
    }
}

// ---------------- GEMM 128x128, 2-term bf16 (A from g_xb, B from g_wh/g_wl) --------
// g_xb @ W -> g_hb.  K chunked by 32 (16 bf16x2 words).
__global__ void __launch_bounds__(256) k_gemm_tc(int layer) {
    __shared__ unsigned sA[128][20];                  // [row][k2] pitch 20
    __shared__ unsigned sBh[16][136], sBl[16][136];   // [k2][n]  pitch 136
    int t = threadIdx.x;
    int rowBase = blockIdx.x * 128;
    int lane = t & 31, w = t >> 5;
    int wm = w >> 1, wn = w & 1;
    int gq = lane >> 2, cq = lane & 3;

    float acc[2][8][4];
    #pragma unroll
    for (int mt = 0; mt < 2; mt++)
        #pragma unroll
        for (int nt = 0; nt < 8; nt++)
            #pragma unroll
            for (int k = 0; k < 4; k++) acc[mt][nt][k] = 0.0f;

    const uint4* X4 = (const uint4*)g_xb;                      // [N][16] uint4
    const uint4* WH = (const uint4*)(g_wh + layer * 64 * HH);  // [64][32] uint4
    const uint4* WL = (const uint4*)(g_wl + layer * 64 * HH);

    for (int kc = 0; kc < 4; kc++) {
        // A: 128 rows x 16 k2-words = 512 uint4; already bf16, direct copy
        #pragma unroll
        for (int i = 0; i < 2; i++) {
            int idx = t + 256 * i;             // 0..511
            int r = idx >> 2, c4 = idx & 3;
            int gr = rowBase + r;
            uint4 v = (gr < NN) ? X4[gr * 16 + kc * 4 + c4]
                                : make_uint4(0u, 0u, 0u, 0u);
            *(uint4*)&sA[r][c4 * 4] = v;
        }
        // B: 16 k2 x 128 n = 512 uint4 each for hi/lo; direct copy
        #pragma unroll
        for (int i = 0; i < 2; i++) {
            int idx = t + 256 * i;             // 0..511
            int k2 = idx >> 5, n4 = idx & 31;  // k2 0..15
            int gsrc = (kc * 16 + k2) * 32 + n4;
            *(uint4*)&sBh[k2][n4 * 4] = WH[gsrc];
            *(uint4*)&sBl[k2][n4 * 4] = WL[gsrc];
        }
        __syncthreads();

        #pragma unroll
        for (int ks = 0; ks < 2; ks++) {
            int kb2 = ks * 8;
            unsigned bh[8][2], bl[8][2];
            #pragma unroll
            for (int nt = 0; nt < 8; nt++) {
                int n0 = wn * 64 + nt * 8 + gq;
                bh[nt][0] = sBh[kb2 + cq][n0];
                bh[nt][1] = sBh[kb2 + 4 + cq][n0];
                bl[nt][0] = sBl[kb2 + cq][n0];
                bl[nt][1] = sBl[kb2 + 4 + cq][n0];
            }
            unsigned ah[2][4];
            #pragma unroll
            for (int mt = 0; mt < 2; mt++) {
                int r0 = wm * 32 + mt * 16 + gq;
                ah[mt][0] = sA[r0][kb2 + cq];
                ah[mt][1] = sA[r0 + 8][kb2 + cq];
                ah[mt][2] = sA[r0][kb2 + 4 + cq];
                ah[mt][3] = sA[r0 + 8][kb2 + 4 + cq];
            }
            #pragma unroll
            for (int mt = 0; mt < 2; mt++)
                #pragma unroll
                for (int nt = 0; nt < 8; nt++) {
                    mma_bf16(acc[mt][nt], ah[mt], bh[nt]);
                    mma_bf16(acc[mt][nt], ah[mt], bl[nt]);
                }
        }
        __syncthreads();
    }

    // epilogue: write g_hb (bf16x2)
    #pragma unroll
    for (int mt = 0; mt < 2; mt++) {
        int r0 = rowBase + wm * 32 + mt * 16 + gq;
        #pragma unroll
        for (int nt = 0; nt < 8; nt++) {
            int col = wn * 64 + nt * 8 + cq * 2;
            if (r0 < NN)
                g_hb[r0 * 64 + (col >> 1)] = packbf2(acc[mt][nt][0], acc[mt][nt][1]);
            if (r0 + 8 < NN)
                g_hb[(r0 + 8) * 64 + (col >> 1)] = packbf2(acc[mt][nt][2], acc[mt][nt][3]);
        }
    }
}

// ---------------- aggregation: half-warp (16 lanes) per node, uint4 gathers ----------
__device__ __forceinline__ void bf8fma(float* acc, float w, uint4 p) {
    acc[0] += w * bflo(p.x);
    acc[1] += w * bfhi(p.x);
    acc[2] += w * bflo(p.y);
    acc[3] += w * bfhi(p.y);
    acc[4] += w * bflo(p.z);
    acc[5] += w * bfhi(p.z);
    acc[6] += w * bflo(p.w);
    acc[7] += w * bfhi(p.w);
}

__global__ void k_agg(const float* __restrict__ bvec,
                      const float* __restrict__ gamma, const float* __restrict__ beta,
                      const float* __restrict__ mean,  const float* __restrict__ var,
                      int residual) {
    int idx = blockIdx.x * blockDim.x + threadIdx.x;
    int node = idx >> 4;
    if (node >= NN) return;
    int l16 = threadIdx.x & 15;
    const uint4* hb4 = (const uint4*)g_hb;   // [N][16] uint4
    uint4* xb4 = (uint4*)g_xb;

    float di = g_dinv[node];
    float self = di * di;
    float acc[8] = {0, 0, 0, 0, 0, 0, 0, 0};
    bf8fma(acc, self, hb4[node * 16 + l16]);

    int s0 = g_off[node], s1 = g_off[node + 1];
    int e = s0;
    for (; e + 2 <= s1; e += 2) {
        int2 sa = g_csr[e];
        int2 sb = g_csr[e + 1];
        uint4 pa = hb4[sa.x * 16 + l16];
        uint4 pb = hb4[sb.x * 16 + l16];
        bf8fma(acc, __int_as_float(sa.y), pa);
        bf8fma(acc, __int_as_float(sb.y), pb);
    }
    if (e < s1) {
        int2 se = g_csr[e];
        bf8fma(acc, __int_as_float(se.y), hb4[se.x * 16 + l16]);
    }

    int c0 = 8 * l16;
    float4 bv0 = *(const float4*)&bvec[c0],  bv1 = *(const float4*)&bvec[c0 + 4];
    float4 gm0 = *(const float4*)&gamma[c0], gm1 = *(const float4*)&gamma[c0 + 4];
    float4 bt0 = *(const float4*)&beta[c0],  bt1 = *(const float4*)&beta[c0 + 4];
    float4 mn0 = *(const float4*)&mean[c0],  mn1 = *(const float4*)&mean[c0 + 4];
    float4 vr0 = *(const float4*)&var[c0],   vr1 = *(const float4*)&var[c0 + 4];

    float b8[8]  = {bv0.x, bv0.y, bv0.z, bv0.w, bv1.x, bv1.y, bv1.z, bv1.w};
    float g8[8]  = {gm0.x, gm0.y, gm0.z, gm0.w, gm1.x, gm1.y, gm1.z, gm1.w};
    float t8[8]  = {bt0.x, bt0.y, bt0.z, bt0.w, bt1.x, bt1.y, bt1.z, bt1.w};
    float m8[8]  = {mn0.x, mn0.y, mn0.z, mn0.w, mn1.x, mn1.y, mn1.z, mn1.w};
    float v8[8]  = {vr0.x, vr0.y, vr0.z, vr0.w, vr1.x, vr1.y, vr1.z, vr1.w};

    float r8[8];
    #pragma unroll
    for (int j = 0; j < 8; j++) {
        float sc = g8[j] * rsqrtf(v8[j] + EPSV);
        r8[j] = fmaxf((acc[j] + b8[j] - m8[j]) * sc + t8[j], 0.0f);
    }

    if (residual) {
        uint4 xp = xb4[node * 16 + l16];
        r8[0] += bflo(xp.x); r8[1] += bfhi(xp.x);
        r8[2] += bflo(xp.y); r8[3] += bfhi(xp.y);
        r8[4] += bflo(xp.z); r8[5] += bfhi(xp.z);
        r8[6] += bflo(xp.w); r8[7] += bfhi(xp.w);
    }
    uint4 outw;
    outw.x = packbf2(r8[0], r8[1]);
    outw.y = packbf2(r8[2], r8[3]);
    outw.z = packbf2(r8[4], r8[5]);
    outw.w = packbf2(r8[6], r8[7]);
    xb4[node * 16 + l16] = outw;
}

// ---------------- fused pooling + MLP head (block per graph) ----------------
__global__ void k_pool_mlp(const float* __restrict__ l1w, const float* __restrict__ l1b,
                           const float* __restrict__ l2w, const float* __restrict__ l2b,
                           float* __restrict__ out) {
    int g = blockIdx.x;
    int t = threadIdx.x;  // 128
    __shared__ float sp[HH];
    __shared__ float red[64];

    int s = g_start[g], e = g_start[g + 1];
    int wi = t >> 1, hi = t & 1;
    float sum = 0.0f;
    for (int r = s; r < e; r++) {
        unsigned w = g_xb[r * 64 + wi];
        sum += hi ? bfhi(w) : bflo(w);
    }
    float inv = 1.0f / fmaxf((float)(e - s), 1.0f);
    sp[t] = sum * inv;
    __syncthreads();

    if (t < 64) {
        float acc = l1b[t];
        #pragma unroll 8
        for (int k = 0; k < HH; k++) acc += sp[k] * l1w[k * 64 + t];
        float h1 = fmaxf(acc, 0.0f);
        red[t] = h1 * l2w[t];
    }
    __syncthreads();
    if (t < 32) {
        float v = red[t] + red[t + 32];
        #pragma unroll
        for (int d = 16; d > 0; d >>= 1) v += __shfl_down_sync(0xFFFFFFFF, v, d);
        if (t == 0) out[g] = v + l2b[0];
    }
}

// ---------------- launch ----------------
extern "C" void kernel_launch(void* const* d_in, const int* in_sizes, int n_in,
                              void* d_out, int out_size) {
    const float* x     = (const float*)d_in[0];
    const int*   ei    = (const int*)d_in[1];
    const int*   batch = (const int*)d_in[2];
    const float* W0    = (const float*)d_in[3];
    const float* b0    = (const float*)d_in[4];
    const float* Ws    = (const float*)d_in[5];
    const float* bs    = (const float*)d_in[6];
    const float* gam   = (const float*)d_in[7];
    const float* bet   = (const float*)d_in[8];
    const float* mean  = (const float*)d_in[9];
    const float* var   = (const float*)d_in[10];
    const float* l1w   = (const float*)d_in[11];
    const float* l1b   = (const float*)d_in[12];
    const float* l2w   = (const float*)d_in[13];
    const float* l2b   = (const float*)d_in[14];
    float* out = (float*)d_out;

    // graph prep + weight pre-split
    k_zero_cnt<<<(NN + 255) / 256, 256>>>();
    k_count<<<(EE + 255) / 256, 256>>>(ei);
    k_scan1<<<SCAN_B, 1024>>>();
    k_scan3<<<(NN + 255) / 256, 256>>>(batch);
    k_fill<<<(EE + 255) / 256, 256>>>(ei);
    k_wsplit<<<((LL - 1) * 64 * HH + 255) / 256, 256>>>(Ws);

    // layer 0
    k_gemm0<<<(NN + 15) / 16, 256>>>(x, W0);
    k_agg<<<(NN * 16 + 255) / 256, 256>>>(b0, gam, bet, mean, var, 0);

    // layers 1..4 (bf16 2-term tensor-core GEMM, pre-split weights)
    for (int l = 1; l < LL; l++) {
        const float* b = bs + (l - 1) * HH;
        k_gemm_tc<<<(NN + 127) / 128, 256>>>(l - 1);
        k_agg<<<(NN * 16 + 255) / 256, 256>>>(b, gam + l * HH, bet + l * HH,
                                              mean + l * HH, var + l * HH, 1);
    }

    // fused pooling + head
    k_pool_mlp<<<GG, 128>>>(l1w, l1b, l2w, l2b, out);
}

// round 15
// speedup vs baseline: 1.0833x; 1.0833x over previous
#include <cuda_runtime.h>
#include <cuda_bf16.h>

#define NN 50000
#define EE 600000
#define HH 128
#define GG 2048
#define FIN 11
#define LL 5
#define EPSV 1e-5f
#define SCAN_B 49            // ceil(NN/1024)
#define WSPL ((LL - 1) * 64 * HH)   // 32768 packed W words
#define BF 2344              // ceil(EE/256) fill blocks

// ---------------- scratch (static device globals) ----------------
__device__ float        g_dinv[NN];
__device__ int          g_cnt[NN];
__device__ int          g_off[NN + 1];
__device__ int          g_cur[NN];
__device__ int2         g_csr[EE];            // {src, nrm-bits}
__device__ unsigned int g_hb[NN * (HH / 2)];  // h  bf16x2, [N][64]
__device__ unsigned int g_xb[NN * (HH / 2)];  // x  bf16x2, [N][64]
__device__ int          g_start[GG + 1];
__device__ int          g_part[64];
__device__ unsigned int g_wh[WSPL];           // W bf16x2 packed along k, [l][k2][n]

// ---------------- bf16 helpers ----------------
__device__ __forceinline__ unsigned packbf2(float a, float b) {
    unsigned r;
    asm("cvt.rn.bf16x2.f32 %0, %1, %2;" : "=r"(r) : "f"(b), "f"(a));
    return r;  // low half = a, high half = b
}
__device__ __forceinline__ float bflo(unsigned w) { return __uint_as_float(w << 16); }
__device__ __forceinline__ float bfhi(unsigned w) { return __uint_as_float(w & 0xFFFF0000u); }

__device__ __forceinline__ void mma_bf16(float* d, const unsigned* a, const unsigned* b) {
    asm volatile(
        "mma.sync.aligned.m16n8k16.row.col.f32.bf16.bf16.f32 "
        "{%0,%1,%2,%3}, {%4,%5,%6,%7}, {%8,%9}, {%0,%1,%2,%3};"
        : "+f"(d[0]), "+f"(d[1]), "+f"(d[2]), "+f"(d[3])
        : "r"(a[0]), "r"(a[1]), "r"(a[2]), "r"(a[3]), "r"(b[0]), "r"(b[1]));
}

// ---------------- prep: zero counts + pack W to bf16 (merged, independent) -------
__global__ void k_zero_wpack(const float* __restrict__ Ws) {
    int i = blockIdx.x * blockDim.x + threadIdx.x;
    if (i < NN) {
        g_cnt[i] = 0;
    } else {
        int idx = i - NN;
        if (idx < WSPL) {
            int n = idx & 127;
            int k2 = (idx >> 7) & 63;
            int l = idx >> 13;
            const float* W = Ws + l * HH * HH;
            float w0 = W[(2 * k2) * HH + n];
            float w1 = W[(2 * k2 + 1) * HH + n];
            g_wh[idx] = packbf2(w0, w1);
        }
    }
}

__global__ void k_count(const int* __restrict__ ei) {
    int e = blockIdx.x * blockDim.x + threadIdx.x;
    if (e < EE) atomicAdd(&g_cnt[ei[EE + e]], 1);
}

// ---- coalesced 2-phase scan (phase 1 also computes dinv) ----
__global__ void k_scan1() {
    int t = threadIdx.x, b = blockIdx.x;
    int i = b * 1024 + t;
    int v = (i < NN) ? g_cnt[i] : 0;
    if (i < NN) g_dinv[i] = rsqrtf((float)v + 1.0f);   // +1 self-loop
    int lane = t & 31, wid = t >> 5;
    int x = v;
    #pragma unroll
    for (int d = 1; d < 32; d <<= 1) {
        int n = __shfl_up_sync(0xFFFFFFFF, x, d);
        if (lane >= d) x += n;
    }
    __shared__ int ws[32];
    if (lane == 31) ws[wid] = x;
    __syncthreads();
    if (wid == 0) {
        int w = ws[lane];
        #pragma unroll
        for (int d = 1; d < 32; d <<= 1) {
            int n = __shfl_up_sync(0xFFFFFFFF, w, d);
            if (lane >= d) w += n;
        }
        ws[lane] = w;
    }
    __syncthreads();
    int incl = x + (wid ? ws[wid - 1] : 0);
    if (i < NN) g_off[i] = incl - v;
    if (t == 1023) g_part[b] = incl;
}

// phase 2: redundant prefix of 49 partials + offsets + per-graph boundaries
__global__ void k_scan3(const int* __restrict__ batch) {
    __shared__ int ps[SCAN_B];
    int t = threadIdx.x;
    if (t == 0) {
        int run = 0;
        #pragma unroll
        for (int j = 0; j < SCAN_B; j++) {
            int v = g_part[j];
            ps[j] = run;
            run += v;
        }
        if (blockIdx.x == 0) g_off[NN] = run;
    }
    __syncthreads();
    int i = blockIdx.x * blockDim.x + t;
    if (i >= NN) return;
    int o = g_off[i] + ps[i >> 10];
    g_off[i] = o;
    g_cur[i] = o;
    int b = batch[i];
    if (i == 0) {
        for (int g = 0; g <= b; g++) g_start[g] = 0;
    } else {
        int pb = batch[i - 1];
        for (int g = pb + 1; g <= b; g++) g_start[g] = i;
    }
    if (i == NN - 1) {
        for (int g = b + 1; g <= GG; g++) g_start[g] = NN;
    }
}

// ---------------- merged: CSR fill (blocks < BF) + layer-0 GEMM (rest) -----------
__global__ void k_fill_gemm0(const int* __restrict__ ei,
                             const float* __restrict__ X, const float* __restrict__ W0) {
    __shared__ float sW[FIN * HH];
    __shared__ float sx[16 * FIN];
    int t = threadIdx.x;
    if (blockIdx.x < BF) {
        int e = blockIdx.x * 256 + t;
        if (e < EE) {
            int s = ei[e];
            int d = ei[EE + e];
            int p = atomicAdd(&g_cur[d], 1);
            g_csr[p] = make_int2(s, __float_as_int(g_dinv[s] * g_dinv[d]));
        }
        return;
    }
    int rowBase = (blockIdx.x - BF) * 16;
    for (int idx = t; idx < FIN * HH; idx += 256) sW[idx] = W0[idx];
    if (t < 16 * FIN) {
        int r = rowBase + t / FIN;
        sx[t] = (r < NN) ? X[r * FIN + (t % FIN)] : 0.0f;
    }
    __syncthreads();
    int c = t & 127;
    int rh = t >> 7;
    float w[FIN];
    #pragma unroll
    for (int k = 0; k < FIN; k++) w[k] = sW[k * HH + c];
    #pragma unroll
    for (int i = 0; i < 8; i++) {
        int rloc = rh + 2 * i;
        int r = rowBase + rloc;
        if (r < NN) {
            float acc = 0.0f;
            #pragma unroll
            for (int k = 0; k < FIN; k++) acc += sx[rloc * FIN + k] * w[k];
            float other = __shfl_xor_sync(0xFFFFFFFF, acc, 1);
            if ((c & 1) == 0)
                g_hb[r * 64 + (c >> 1)] = packbf2(acc, other);
        }
    }
}

// ---------------- GEMM 128x128, single-term bf16: g_xb @ W -> g_hb --------------
// K chunked by 32 (16 bf16x2 words).
__global__ void __launch_bounds__(256) k_gemm_tc(int layer) {
    __shared__ unsigned sA[128][20];     // [row][k2] pitch 20
    __shared__ unsigned sB[16][136];     // [k2][n]  pitch 136
    int t = threadIdx.x;
    int rowBase = blockIdx.x * 128;
    int lane = t & 31, w = t >> 5;
    int wm = w >> 1, wn = w & 1;
    int gq = lane >> 2, cq = lane & 3;

    float acc[2][8][4];
    #pragma unroll
    for (int mt = 0; mt < 2; mt++)
        #pragma unroll
        for (int nt = 0; nt < 8; nt++)
            #pragma unroll
            for (int k = 0; k < 4; k++) acc[mt][nt][k] = 0.0f;

    const uint4* X4 = (const uint4*)g_xb;                      // [N][16] uint4
    const uint4* WH = (const uint4*)(g_wh + layer * 64 * HH);  // [64][32] uint4

    for (int kc = 0; kc < 4; kc++) {
        #pragma unroll
        for (int i = 0; i < 2; i++) {
            int idx = t + 256 * i;             // 0..511
            int r = idx >> 2, c4 = idx & 3;
            int gr = rowBase + r;
            uint4 v = (gr < NN) ? X4[gr * 16 + kc * 4 + c4]
                                : make_uint4(0u, 0u, 0u, 0u);
            *(uint4*)&sA[r][c4 * 4] = v;
        }
        #pragma unroll
        for (int i = 0; i < 2; i++) {
            int idx = t + 256 * i;             // 0..511
            int k2 = idx >> 5, n4 = idx & 31;  // k2 0..15
            *(uint4*)&sB[k2][n4 * 4] = WH[(kc * 16 + k2) * 32 + n4];
        }
        __syncthreads();

        #pragma unroll
        for (int ks = 0; ks < 2; ks++) {
            int kb2 = ks * 8;
            unsigned bh[8][2];
            #pragma unroll
            for (int nt = 0; nt < 8; nt++) {
                int n0 = wn * 64 + nt * 8 + gq;
                bh[nt][0] = sB[kb2 + cq][n0];
                bh[nt][1] = sB[kb2 + 4 + cq][n0];
            }
            unsigned ah[2][4];
            #pragma unroll
            for (int mt = 0; mt < 2; mt++) {
                int r0 = wm * 32 + mt * 16 + gq;
                ah[mt][0] = sA[r0][kb2 + cq];
                ah[mt][1] = sA[r0 + 8][kb2 + cq];
                ah[mt][2] = sA[r0][kb2 + 4 + cq];
                ah[mt][3] = sA[r0 + 8][kb2 + 4 + cq];
            }
            #pragma unroll
            for (int mt = 0; mt < 2; mt++)
                #pragma unroll
                for (int nt = 0; nt < 8; nt++)
                    mma_bf16(acc[mt][nt], ah[mt], bh[nt]);
        }
        __syncthreads();
    }

    // epilogue: write g_hb (bf16x2)
    #pragma unroll
    for (int mt = 0; mt < 2; mt++) {
        int r0 = rowBase + wm * 32 + mt * 16 + gq;
        #pragma unroll
        for (int nt = 0; nt < 8; nt++) {
            int col = wn * 64 + nt * 8 + cq * 2;
            if (r0 < NN)
                g_hb[r0 * 64 + (col >> 1)] = packbf2(acc[mt][nt][0], acc[mt][nt][1]);
            if (r0 + 8 < NN)
                g_hb[(r0 + 8) * 64 + (col >> 1)] = packbf2(acc[mt][nt][2], acc[mt][nt][3]);
        }
    }
}

// ---------------- aggregation: half-warp (16 lanes) per node, uint4 gathers ----------
__device__ __forceinline__ void bf8fma(float* acc, float w, uint4 p) {
    acc[0] += w * bflo(p.x);
    acc[1] += w * bfhi(p.x);
    acc[2] += w * bflo(p.y);
    acc[3] += w * bfhi(p.y);
    acc[4] += w * bflo(p.z);
    acc[5] += w * bfhi(p.z);
    acc[6] += w * bflo(p.w);
    acc[7] += w * bfhi(p.w);
}

__global__ void k_agg(const float* __restrict__ bvec,
                      const float* __restrict__ gamma, const float* __restrict__ beta,
                      const float* __restrict__ mean,  const float* __restrict__ var,
                      int residual) {
    int idx = blockIdx.x * blockDim.x + threadIdx.x;
    int node = idx >> 4;
    if (node >= NN) return;
    int l16 = threadIdx.x & 15;
    const uint4* hb4 = (const uint4*)g_hb;   // [N][16] uint4
    uint4* xb4 = (uint4*)g_xb;

    float di = g_dinv[node];
    float self = di * di;
    float acc[8] = {0, 0, 0, 0, 0, 0, 0, 0};
    bf8fma(acc, self, hb4[node * 16 + l16]);

    int s0 = g_off[node], s1 = g_off[node + 1];
    int e = s0;
    for (; e + 2 <= s1; e += 2) {
        int2 sa = g_csr[e];
        int2 sb = g_csr[e + 1];
        uint4 pa = hb4[sa.x * 16 + l16];
        uint4 pb = hb4[sb.x * 16 + l16];
        bf8fma(acc, __int_as_float(sa.y), pa);
        bf8fma(acc, __int_as_float(sb.y), pb);
    }
    if (e < s1) {
        int2 se = g_csr[e];
        bf8fma(acc, __int_as_float(se.y), hb4[se.x * 16 + l16]);
    }

    int c0 = 8 * l16;
    float4 bv0 = *(const float4*)&bvec[c0],  bv1 = *(const float4*)&bvec[c0 + 4];
    float4 gm0 = *(const float4*)&gamma[c0], gm1 = *(const float4*)&gamma[c0 + 4];
    float4 bt0 = *(const float4*)&beta[c0],  bt1 = *(const float4*)&beta[c0 + 4];
    float4 mn0 = *(const float4*)&mean[c0],  mn1 = *(const float4*)&mean[c0 + 4];
    float4 vr0 = *(const float4*)&var[c0],   vr1 = *(const float4*)&var[c0 + 4];

    float b8[8]  = {bv0.x, bv0.y, bv0.z, bv0.w, bv1.x, bv1.y, bv1.z, bv1.w};
    float g8[8]  = {gm0.x, gm0.y, gm0.z, gm0.w, gm1.x, gm1.y, gm1.z, gm1.w};
    float t8[8]  = {bt0.x, bt0.y, bt0.z, bt0.w, bt1.x, bt1.y, bt1.z, bt1.w};
    float m8[8]  = {mn0.x, mn0.y, mn0.z, mn0.w, mn1.x, mn1.y, mn1.z, mn1.w};
    float v8[8]  = {vr0.x, vr0.y, vr0.z, vr0.w, vr1.x, vr1.y, vr1.z, vr1.w};

    float r8[8];
    #pragma unroll
    for (int j = 0; j < 8; j++) {
        float sc = g8[j] * rsqrtf(v8[j] + EPSV);
        r8[j] = fmaxf((acc[j] + b8[j] - m8[j]) * sc + t8[j], 0.0f);
    }

    if (residual) {
        uint4 xp = xb4[node * 16 + l16];
        r8[0] += bflo(xp.x); r8[1] += bfhi(xp.x);
        r8[2] += bflo(xp.y); r8[3] += bfhi(xp.y);
        r8[4] += bflo(xp.z); r8[5] += bfhi(xp.z);
        r8[6] += bflo(xp.w); r8[7] += bfhi(xp.w);
    }
    uint4 outw;
    outw.x = packbf2(r8[0], r8[1]);
    outw.y = packbf2(r8[2], r8[3]);
    outw.z = packbf2(r8[4], r8[5]);
    outw.w = packbf2(r8[6], r8[7]);
    xb4[node * 16 + l16] = outw;
}

// ---------------- fused pooling + MLP head (block per graph) ----------------
__global__ void k_pool_mlp(const float* __restrict__ l1w, const float* __restrict__ l1b,
                           const float* __restrict__ l2w, const float* __restrict__ l2b,
                           float* __restrict__ out) {
    int g = blockIdx.x;
    int t = threadIdx.x;  // 128
    __shared__ float sp[HH];
    __shared__ float red[64];

    int s = g_start[g], e = g_start[g + 1];
    int wi = t >> 1, hi = t & 1;
    float sum = 0.0f;
    for (int r = s; r < e; r++) {
        unsigned w = g_xb[r * 64 + wi];
        sum += hi ? bfhi(w) : bflo(w);
    }
    float inv = 1.0f / fmaxf((float)(e - s), 1.0f);
    sp[t] = sum * inv;
    __syncthreads();

    if (t < 64) {
        float acc = l1b[t];
        #pragma unroll 8
        for (int k = 0; k < HH; k++) acc += sp[k] * l1w[k * 64 + t];
        float h1 = fmaxf(acc, 0.0f);
        red[t] = h1 * l2w[t];
    }
    __syncthreads();
    if (t < 32) {
        float v = red[t] + red[t + 32];
        #pragma unroll
        for (int d = 16; d > 0; d >>= 1) v += __shfl_down_sync(0xFFFFFFFF, v, d);
        if (t == 0) out[g] = v + l2b[0];
    }
}

// ---------------- launch ----------------
extern "C" void kernel_launch(void* const* d_in, const int* in_sizes, int n_in,
                              void* d_out, int out_size) {
    const float* x     = (const float*)d_in[0];
    const int*   ei    = (const int*)d_in[1];
    const int*   batch = (const int*)d_in[2];
    const float* W0    = (const float*)d_in[3];
    const float* b0    = (const float*)d_in[4];
    const float* Ws    = (const float*)d_in[5];
    const float* bs    = (const float*)d_in[6];
    const float* gam   = (const float*)d_in[7];
    const float* bet   = (const float*)d_in[8];
    const float* mean  = (const float*)d_in[9];
    const float* var   = (const float*)d_in[10];
    const float* l1w   = (const float*)d_in[11];
    const float* l1b   = (const float*)d_in[12];
    const float* l2w   = (const float*)d_in[13];
    const float* l2b   = (const float*)d_in[14];
    float* out = (float*)d_out;

    // graph prep (zero+wpack merged)
    k_zero_wpack<<<(NN + WSPL + 255) / 256, 256>>>(Ws);
    k_count<<<(EE + 255) / 256, 256>>>(ei);
    k_scan1<<<SCAN_B, 1024>>>();
    k_scan3<<<(NN + 255) / 256, 256>>>(batch);

    // CSR fill + layer-0 GEMM (merged)
    k_fill_gemm0<<<BF + (NN + 15) / 16, 256>>>(ei, x, W0);
    k_agg<<<(NN * 16 + 255) / 256, 256>>>(b0, gam, bet, mean, var, 0);

    // layers 1..4 (single-term bf16 tensor-core GEMM)
    for (int l = 1; l < LL; l++) {
        const float* b = bs + (l - 1) * HH;
        k_gemm_tc<<<(NN + 127) / 128, 256>>>(l - 1);
        k_agg<<<(NN * 16 + 255) / 256, 256>>>(b, gam + l * HH, bet + l * HH,
                                              mean + l * HH, var + l * HH, 1);
    }

    // fused pooling + head
    k_pool_mlp<<<GG, 128>>>(l1w, l1b, l2w, l2b, out);
}

// round 16
// speedup vs baseline: 1.0836x; 1.0003x over previous
#include <cuda_runtime.h>
#include <cuda_bf16.h>

#define NN 50000
#define EE 600000
#define HH 128
#define GG 2048
#define FIN 11
#define LL 5
#define EPSV 1e-5f
#define SCAN_B 49            // ceil(NN/1024)
#define WSPL ((LL - 1) * 64 * HH)   // 32768 packed W words
#define BF 2344              // ceil(EE/256) fill blocks

// ---------------- scratch (static device globals) ----------------
__device__ float        g_dinv[NN];
__device__ int          g_cnt[NN];
__device__ int          g_off[NN + 1];
__device__ int          g_cur[NN];
__device__ int2         g_csr[EE];            // {src, nrm-bits}
__device__ unsigned int g_hb[NN * (HH / 2)];  // h  bf16x2, [N][64]
__device__ unsigned int g_xb[NN * (HH / 2)];  // x  bf16x2, [N][64]
__device__ int          g_start[GG + 1];
__device__ int          g_part[64];
__device__ unsigned int g_wh[WSPL];           // W bf16x2 packed along k, [l][k2][n]

// ---------------- bf16 helpers ----------------
__device__ __forceinline__ unsigned packbf2(float a, float b) {
    unsigned r;
    asm("cvt.rn.bf16x2.f32 %0, %1, %2;" : "=r"(r) : "f"(b), "f"(a));
    return r;  // low half = a, high half = b
}
__device__ __forceinline__ float bflo(unsigned w) { return __uint_as_float(w << 16); }
__device__ __forceinline__ float bfhi(unsigned w) { return __uint_as_float(w & 0xFFFF0000u); }

__device__ __forceinline__ void mma_bf16(float* d, const unsigned* a, const unsigned* b) {
    asm volatile(
        "mma.sync.aligned.m16n8k16.row.col.f32.bf16.bf16.f32 "
        "{%0,%1,%2,%3}, {%4,%5,%6,%7}, {%8,%9}, {%0,%1,%2,%3};"
        : "+f"(d[0]), "+f"(d[1]), "+f"(d[2]), "+f"(d[3])
        : "r"(a[0]), "r"(a[1]), "r"(a[2]), "r"(a[3]), "r"(b[0]), "r"(b[1]));
}

// ---------------- prep: zero counts + pack W to bf16 (merged, independent) -------
__global__ void k_zero_wpack(const float* __restrict__ Ws) {
    int i = blockIdx.x * blockDim.x + threadIdx.x;
    if (i < NN) {
        g_cnt[i] = 0;
    } else {
        int idx = i - NN;
        if (idx < WSPL) {
            int n = idx & 127;
            int k2 = (idx >> 7) & 63;
            int l = idx >> 13;
            const float* W = Ws + l * HH * HH;
            float w0 = W[(2 * k2) * HH + n];
            float w1 = W[(2 * k2 + 1) * HH + n];
            g_wh[idx] = packbf2(w0, w1);
        }
    }
}

__global__ void k_count(const int* __restrict__ ei) {
    int e = blockIdx.x * blockDim.x + threadIdx.x;
    if (e < EE) atomicAdd(&g_cnt[ei[EE + e]], 1);
}

// ---- coalesced 2-phase scan (phase 1 also computes dinv) ----
__global__ void k_scan1() {
    int t = threadIdx.x, b = blockIdx.x;
    int i = b * 1024 + t;
    int v = (i < NN) ? g_cnt[i] : 0;
    if (i < NN) g_dinv[i] = rsqrtf((float)v + 1.0f);   // +1 self-loop
    int lane = t & 31, wid = t >> 5;
    int x = v;
    #pragma unroll
    for (int d = 1; d < 32; d <<= 1) {
        int n = __shfl_up_sync(0xFFFFFFFF, x, d);
        if (lane >= d) x += n;
    }
    __shared__ int ws[32];
    if (lane == 31) ws[wid] = x;
    __syncthreads();
    if (wid == 0) {
        int w = ws[lane];
        #pragma unroll
        for (int d = 1; d < 32; d <<= 1) {
            int n = __shfl_up_sync(0xFFFFFFFF, w, d);
            if (lane >= d) w += n;
        }
        ws[lane] = w;
    }
    __syncthreads();
    int incl = x + (wid ? ws[wid - 1] : 0);
    if (i < NN) g_off[i] = incl - v;
    if (t == 1023) g_part[b] = incl;
}

// phase 2: warp-parallel prefix of 49 partials + offsets + per-graph boundaries
__global__ void k_scan3(const int* __restrict__ batch) {
    __shared__ int ps[64];
    int t = threadIdx.x;
    if (t < 32) {
        int a0 = (2 * t     < SCAN_B) ? g_part[2 * t]     : 0;
        int a1 = (2 * t + 1 < SCAN_B) ? g_part[2 * t + 1] : 0;
        int s = a0 + a1;
        int x = s;
        #pragma unroll
        for (int d = 1; d < 32; d <<= 1) {
            int n = __shfl_up_sync(0xFFFFFFFF, x, d);
            if (t >= d) x += n;
        }
        int excl = x - s;
        ps[2 * t] = excl;
        ps[2 * t + 1] = excl + a0;
        if (t == 31 && blockIdx.x == 0) g_off[NN] = x;
    }
    __syncthreads();
    int i = blockIdx.x * blockDim.x + t;
    if (i >= NN) return;
    int o = g_off[i] + ps[i >> 10];
    g_off[i] = o;
    g_cur[i] = o;
    int b = batch[i];
    if (i == 0) {
        for (int g = 0; g <= b; g++) g_start[g] = 0;
    } else {
        int pb = batch[i - 1];
        for (int g = pb + 1; g <= b; g++) g_start[g] = i;
    }
    if (i == NN - 1) {
        for (int g = b + 1; g <= GG; g++) g_start[g] = NN;
    }
}

// ---------------- merged: CSR fill (blocks < BF) + layer-0 GEMM (rest) -----------
__global__ void k_fill_gemm0(const int* __restrict__ ei,
                             const float* __restrict__ X, const float* __restrict__ W0) {
    __shared__ float sW[FIN * HH];
    __shared__ float sx[16 * FIN];
    int t = threadIdx.x;
    if (blockIdx.x < BF) {
        int e = blockIdx.x * 256 + t;
        if (e < EE) {
            int s = ei[e];
            int d = ei[EE + e];
            int p = atomicAdd(&g_cur[d], 1);
            g_csr[p] = make_int2(s, __float_as_int(g_dinv[s] * g_dinv[d]));
        }
        return;
    }
    int rowBase = (blockIdx.x - BF) * 16;
    for (int idx = t; idx < FIN * HH; idx += 256) sW[idx] = W0[idx];
    if (t < 16 * FIN) {
        int r = rowBase + t / FIN;
        sx[t] = (r < NN) ? X[r * FIN + (t % FIN)] : 0.0f;
    }
    __syncthreads();
    int c = t & 127;
    int rh = t >> 7;
    float w[FIN];
    #pragma unroll
    for (int k = 0; k < FIN; k++) w[k] = sW[k * HH + c];
    #pragma unroll
    for (int i = 0; i < 8; i++) {
        int rloc = rh + 2 * i;
        int r = rowBase + rloc;
        if (r < NN) {
            float acc = 0.0f;
            #pragma unroll
            for (int k = 0; k < FIN; k++) acc += sx[rloc * FIN + k] * w[k];
            float other = __shfl_xor_sync(0xFFFFFFFF, acc, 1);
            if ((c & 1) == 0)
                g_hb[r * 64 + (c >> 1)] = packbf2(acc, other);
        }
    }
}

// ---------------- GEMM 128x128, single-term bf16: g_xb @ W -> g_hb --------------
__global__ void __launch_bounds__(256) k_gemm_tc(int layer) {
    __shared__ unsigned sA[128][20];     // [row][k2] pitch 20
    __shared__ unsigned sB[16][136];     // [k2][n]  pitch 136
    int t = threadIdx.x;
    int rowBase = blockIdx.x * 128;
    int lane = t & 31, w = t >> 5;
    int wm = w >> 1, wn = w & 1;
    int gq = lane >> 2, cq = lane & 3;

    float acc[2][8][4];
    #pragma unroll
    for (int mt = 0; mt < 2; mt++)
        #pragma unroll
        for (int nt = 0; nt < 8; nt++)
            #pragma unroll
            for (int k = 0; k < 4; k++) acc[mt][nt][k] = 0.0f;

    const uint4* X4 = (const uint4*)g_xb;                      // [N][16] uint4
    const uint4* WH = (const uint4*)(g_wh + layer * 64 * HH);  // [64][32] uint4

    for (int kc = 0; kc < 4; kc++) {
        #pragma unroll
        for (int i = 0; i < 2; i++) {
            int idx = t + 256 * i;             // 0..511
            int r = idx >> 2, c4 = idx & 3;
            int gr = rowBase + r;
            uint4 v = (gr < NN) ? X4[gr * 16 + kc * 4 + c4]
                                : make_uint4(0u, 0u, 0u, 0u);
            *(uint4*)&sA[r][c4 * 4] = v;
        }
        #pragma unroll
        for (int i = 0; i < 2; i++) {
            int idx = t + 256 * i;             // 0..511
            int k2 = idx >> 5, n4 = idx & 31;  // k2 0..15
            *(uint4*)&sB[k2][n4 * 4] = WH[(kc * 16 + k2) * 32 + n4];
        }
        __syncthreads();

        #pragma unroll
        for (int ks = 0; ks < 2; ks++) {
            int kb2 = ks * 8;
            unsigned bh[8][2];
            #pragma unroll
            for (int nt = 0; nt < 8; nt++) {
                int n0 = wn * 64 + nt * 8 + gq;
                bh[nt][0] = sB[kb2 + cq][n0];
                bh[nt][1] = sB[kb2 + 4 + cq][n0];
            }
            unsigned ah[2][4];
            #pragma unroll
            for (int mt = 0; mt < 2; mt++) {
                int r0 = wm * 32 + mt * 16 + gq;
                ah[mt][0] = sA[r0][kb2 + cq];
                ah[mt][1] = sA[r0 + 8][kb2 + cq];
                ah[mt][2] = sA[r0][kb2 + 4 + cq];
                ah[mt][3] = sA[r0 + 8][kb2 + 4 + cq];
            }
            #pragma unroll
            for (int mt = 0; mt < 2; mt++)
                #pragma unroll
                for (int nt = 0; nt < 8; nt++)
                    mma_bf16(acc[mt][nt], ah[mt], bh[nt]);
        }
        __syncthreads();
    }

    #pragma unroll
    for (int mt = 0; mt < 2; mt++) {
        int r0 = rowBase + wm * 32 + mt * 16 + gq;
        #pragma unroll
        for (int nt = 0; nt < 8; nt++) {
            int col = wn * 64 + nt * 8 + cq * 2;
            if (r0 < NN)
                g_hb[r0 * 64 + (col >> 1)] = packbf2(acc[mt][nt][0], acc[mt][nt][1]);
            if (r0 + 8 < NN)
                g_hb[(r0 + 8) * 64 + (col >> 1)] = packbf2(acc[mt][nt][2], acc[mt][nt][3]);
        }
    }
}

// ---------------- aggregation: half-warp per node, uint4 gathers, 4x unroll ---------
__device__ __forceinline__ void bf8fma(float* acc, float w, uint4 p) {
    acc[0] += w * bflo(p.x);
    acc[1] += w * bfhi(p.x);
    acc[2] += w * bflo(p.y);
    acc[3] += w * bfhi(p.y);
    acc[4] += w * bflo(p.z);
    acc[5] += w * bfhi(p.z);
    acc[6] += w * bflo(p.w);
    acc[7] += w * bfhi(p.w);
}

__global__ void k_agg(const float* __restrict__ bvec,
                      const float* __restrict__ gamma, const float* __restrict__ beta,
                      const float* __restrict__ mean,  const float* __restrict__ var,
                      int residual) {
    int idx = blockIdx.x * blockDim.x + threadIdx.x;
    int node = idx >> 4;
    if (node >= NN) return;
    int l16 = threadIdx.x & 15;
    const uint4* hb4 = (const uint4*)g_hb;   // [N][16] uint4
    uint4* xb4 = (uint4*)g_xb;

    float di = g_dinv[node];
    float self = di * di;
    float acc[8] = {0, 0, 0, 0, 0, 0, 0, 0};
    bf8fma(acc, self, hb4[node * 16 + l16]);

    int s0 = g_off[node], s1 = g_off[node + 1];
    int e = s0;
    for (; e + 4 <= s1; e += 4) {
        int2 sa = g_csr[e];
        int2 sb = g_csr[e + 1];
        int2 sc = g_csr[e + 2];
        int2 sd = g_csr[e + 3];
        uint4 pa = hb4[sa.x * 16 + l16];
        uint4 pb = hb4[sb.x * 16 + l16];
        uint4 pc = hb4[sc.x * 16 + l16];
        uint4 pd = hb4[sd.x * 16 + l16];
        bf8fma(acc, __int_as_float(sa.y), pa);
        bf8fma(acc, __int_as_float(sb.y), pb);
        bf8fma(acc, __int_as_float(sc.y), pc);
        bf8fma(acc, __int_as_float(sd.y), pd);
    }
    if (e + 2 <= s1) {
        int2 sa = g_csr[e];
        int2 sb = g_csr[e + 1];
        uint4 pa = hb4[sa.x * 16 + l16];
        uint4 pb = hb4[sb.x * 16 + l16];
        bf8fma(acc, __int_as_float(sa.y), pa);
        bf8fma(acc, __int_as_float(sb.y), pb);
        e += 2;
    }
    if (e < s1) {
        int2 se = g_csr[e];
        bf8fma(acc, __int_as_float(se.y), hb4[se.x * 16 + l16]);
    }

    int c0 = 8 * l16;
    float4 bv0 = *(const float4*)&bvec[c0],  bv1 = *(const float4*)&bvec[c0 + 4];
    float4 gm0 = *(const float4*)&gamma[c0], gm1 = *(const float4*)&gamma[c0 + 4];
    float4 bt0 = *(const float4*)&beta[c0],  bt1 = *(const float4*)&beta[c0 + 4];
    float4 mn0 = *(const float4*)&mean[c0],  mn1 = *(const float4*)&mean[c0 + 4];
    float4 vr0 = *(const float4*)&var[c0],   vr1 = *(const float4*)&var[c0 + 4];

    float b8[8]  = {bv0.x, bv0.y, bv0.z, bv0.w, bv1.x, bv1.y, bv1.z, bv1.w};
    float g8[8]  = {gm0.x, gm0.y, gm0.z, gm0.w, gm1.x, gm1.y, gm1.z, gm1.w};
    float t8[8]  = {bt0.x, bt0.y, bt0.z, bt0.w, bt1.x, bt1.y, bt1.z, bt1.w};
    float m8[8]  = {mn0.x, mn0.y, mn0.z, mn0.w, mn1.x, mn1.y, mn1.z, mn1.w};
    float v8[8]  = {vr0.x, vr0.y, vr0.z, vr0.w, vr1.x, vr1.y, vr1.z, vr1.w};

    float r8[8];
    #pragma unroll
    for (int j = 0; j < 8; j++) {
        float sc = g8[j] * rsqrtf(v8[j] + EPSV);
        r8[j] = fmaxf((acc[j] + b8[j] - m8[j]) * sc + t8[j], 0.0f);
    }

    if (residual) {
        uint4 xp = xb4[node * 16 + l16];
        r8[0] += bflo(xp.x); r8[1] += bfhi(xp.x);
        r8[2] += bflo(xp.y); r8[3] += bfhi(xp.y);
        r8[4] += bflo(xp.z); r8[5] += bfhi(xp.z);
        r8[6] += bflo(xp.w); r8[7] += bfhi(xp.w);
    }
    uint4 outw;
    outw.x = packbf2(r8[0], r8[1]);
    outw.y = packbf2(r8[2], r8[3]);
    outw.z = packbf2(r8[4], r8[5]);
    outw.w = packbf2(r8[6], r8[7]);
    xb4[node * 16 + l16] = outw;
}

// ---------------- fused pooling + MLP head (block per graph) ----------------
__global__ void k_pool_mlp(const float* __restrict__ l1w, const float* __restrict__ l1b,
                           const float* __restrict__ l2w, const float* __restrict__ l2b,
                           float* __restrict__ out) {
    int g = blockIdx.x;
    int t = threadIdx.x;  // 128
    __shared__ float sp[HH];
    __shared__ float red[64];

    int s = g_start[g], e = g_start[g + 1];
    int wi = t >> 1, hi = t & 1;
    float sum = 0.0f;
    for (int r = s; r < e; r++) {
        unsigned w = g_xb[r * 64 + wi];
        sum += hi ? bfhi(w) : bflo(w);
    }
    float inv = 1.0f / fmaxf((float)(e - s), 1.0f);
    sp[t] = sum * inv;
    __syncthreads();

    if (t < 64) {
        float acc = l1b[t];
        #pragma unroll 8
        for (int k = 0; k < HH; k++) acc += sp[k] * l1w[k * 64 + t];
        float h1 = fmaxf(acc, 0.0f);
        red[t] = h1 * l2w[t];
    }
    __syncthreads();
    if (t < 32) {
        float v = red[t] + red[t + 32];
        #pragma unroll
        for (int d = 16; d > 0; d >>= 1) v += __shfl_down_sync(0xFFFFFFFF, v, d);
        if (t == 0) out[g] = v + l2b[0];
    }
}

// ---------------- launch ----------------
extern "C" void kernel_launch(void* const* d_in, const int* in_sizes, int n_in,
                              void* d_out, int out_size) {
    const float* x     = (const float*)d_in[0];
    const int*   ei    = (const int*)d_in[1];
    const int*   batch = (const int*)d_in[2];
    const float* W0    = (const float*)d_in[3];
    const float* b0    = (const float*)d_in[4];
    const float* Ws    = (const float*)d_in[5];
    const float* bs    = (const float*)d_in[6];
    const float* gam   = (const float*)d_in[7];
    const float* bet   = (const float*)d_in[8];
    const float* mean  = (const float*)d_in[9];
    const float* var   = (const float*)d_in[10];
    const float* l1w   = (const float*)d_in[11];
    const float* l1b   = (const float*)d_in[12];
    const float* l2w   = (const float*)d_in[13];
    const float* l2b   = (const float*)d_in[14];
    float* out = (float*)d_out;

    // graph prep
    k_zero_wpack<<<(NN + WSPL + 255) / 256, 256>>>(Ws);
    k_count<<<(EE + 255) / 256, 256>>>(ei);
    k_scan1<<<SCAN_B, 1024>>>();
    k_scan3<<<(NN + 255) / 256, 256>>>(batch);

    // CSR fill + layer-0 GEMM (merged)
    k_fill_gemm0<<<BF + (NN + 15) / 16, 256>>>(ei, x, W0);
    k_agg<<<(NN * 16 + 255) / 256, 256>>>(b0, gam, bet, mean, var, 0);

    // layers 1..4 (single-term bf16 tensor-core GEMM)
    for (int l = 1; l < LL; l++) {
        const float* b = bs + (l - 1) * HH;
        k_gemm_tc<<<(NN + 127) / 128, 256>>>(l - 1);
        k_agg<<<(NN * 16 + 255) / 256, 256>>>(b, gam + l * HH, bet + l * HH,
                                              mean + l * HH, var + l * HH, 1);
    }

    // fused pooling + head
    k_pool_mlp<<<GG, 128>>>(l1w, l1b, l2w, l2b, out);
}

// round 17
// speedup vs baseline: 1.1169x; 1.0308x over previous
#include <cuda_runtime.h>
#include <cuda_bf16.h>

#define NN 50000
#define EE 600000
#define HH 128
#define GG 2048
#define FIN 11
#define LL 5
#define EPSV 1e-5f
#define SCAN_B 49            // ceil(NN/1024)
#define WSPL ((LL - 1) * 64 * HH)   // 32768 packed W words
#define BF 2344              // ceil(EE/256) fill blocks

#define GDC_WAIT() asm volatile("griddepcontrol.wait;" ::: "memory")

// ---------------- scratch (static device globals) ----------------
__device__ float        g_dinv[NN];
__device__ int          g_cnt[NN];
__device__ int          g_off[NN + 1];
__device__ int          g_cur[NN];
__device__ int2         g_csr[EE];            // {src, nrm-bits}
__device__ unsigned int g_hb[NN * (HH / 2)];  // h  bf16x2, [N][64]
__device__ unsigned int g_xb[NN * (HH / 2)];  // x  bf16x2, [N][64]
__device__ int          g_start[GG + 1];
__device__ int          g_part[64];
__device__ unsigned int g_wh[WSPL];           // W bf16x2 packed along k, [l][k2][n]

// ---------------- bf16 helpers ----------------
__device__ __forceinline__ unsigned packbf2(float a, float b) {
    unsigned r;
    asm("cvt.rn.bf16x2.f32 %0, %1, %2;" : "=r"(r) : "f"(b), "f"(a));
    return r;  // low half = a, high half = b
}
__device__ __forceinline__ float bflo(unsigned w) { return __uint_as_float(w << 16); }
__device__ __forceinline__ float bfhi(unsigned w) { return __uint_as_float(w & 0xFFFF0000u); }

__device__ __forceinline__ void mma_bf16(float* d, const unsigned* a, const unsigned* b) {
    asm volatile(
        "mma.sync.aligned.m16n8k16.row.col.f32.bf16.bf16.f32 "
        "{%0,%1,%2,%3}, {%4,%5,%6,%7}, {%8,%9}, {%0,%1,%2,%3};"
        : "+f"(d[0]), "+f"(d[1]), "+f"(d[2]), "+f"(d[3])
        : "r"(a[0]), "r"(a[1]), "r"(a[2]), "r"(a[3]), "r"(b[0]), "r"(b[1]));
}

// ---------------- prep: zero counts + pack W to bf16 (merged, independent) -------
__global__ void k_zero_wpack(const float* __restrict__ Ws) {
    GDC_WAIT();
    int i = blockIdx.x * blockDim.x + threadIdx.x;
    if (i < NN) {
        g_cnt[i] = 0;
    } else {
        int idx = i - NN;
        if (idx < WSPL) {
            int n = idx & 127;
            int k2 = (idx >> 7) & 63;
            int l = idx >> 13;
            const float* W = Ws + l * HH * HH;
            float w0 = W[(2 * k2) * HH + n];
            float w1 = W[(2 * k2 + 1) * HH + n];
            g_wh[idx] = packbf2(w0, w1);
        }
    }
}

__global__ void k_count(const int* __restrict__ ei) {
    GDC_WAIT();
    int e = blockIdx.x * blockDim.x + threadIdx.x;
    if (e < EE) atomicAdd(&g_cnt[ei[EE + e]], 1);
}

// ---- coalesced 2-phase scan (phase 1 also computes dinv) ----
__global__ void k_scan1() {
    GDC_WAIT();
    int t = threadIdx.x, b = blockIdx.x;
    int i = b * 1024 + t;
    int v = (i < NN) ? g_cnt[i] : 0;
    if (i < NN) g_dinv[i] = rsqrtf((float)v + 1.0f);   // +1 self-loop
    int lane = t & 31, wid = t >> 5;
    int x = v;
    #pragma unroll
    for (int d = 1; d < 32; d <<= 1) {
        int n = __shfl_up_sync(0xFFFFFFFF, x, d);
        if (lane >= d) x += n;
    }
    __shared__ int ws[32];
    if (lane == 31) ws[wid] = x;
    __syncthreads();
    if (wid == 0) {
        int w = ws[lane];
        #pragma unroll
        for (int d = 1; d < 32; d <<= 1) {
            int n = __shfl_up_sync(0xFFFFFFFF, w, d);
            if (lane >= d) w += n;
        }
        ws[lane] = w;
    }
    __syncthreads();
    int incl = x + (wid ? ws[wid - 1] : 0);
    if (i < NN) g_off[i] = incl - v;
    if (t == 1023) g_part[b] = incl;
}

// phase 2: warp-parallel prefix of 49 partials + offsets + per-graph boundaries
__global__ void k_scan3(const int* __restrict__ batch) {
    GDC_WAIT();
    __shared__ int ps[64];
    int t = threadIdx.x;
    if (t < 32) {
        int a0 = (2 * t     < SCAN_B) ? g_part[2 * t]     : 0;
        int a1 = (2 * t + 1 < SCAN_B) ? g_part[2 * t + 1] : 0;
        int s = a0 + a1;
        int x = s;
        #pragma unroll
        for (int d = 1; d < 32; d <<= 1) {
            int n = __shfl_up_sync(0xFFFFFFFF, x, d);
            if (t >= d) x += n;
        }
        int excl = x - s;
        ps[2 * t] = excl;
        ps[2 * t + 1] = excl + a0;
        if (t == 31 && blockIdx.x == 0) g_off[NN] = x;
    }
    __syncthreads();
    int i = blockIdx.x * blockDim.x + t;
    if (i >= NN) return;
    int o = g_off[i] + ps[i >> 10];
    g_off[i] = o;
    g_cur[i] = o;
    int b = batch[i];
    if (i == 0) {
        for (int g = 0; g <= b; g++) g_start[g] = 0;
    } else {
        int pb = batch[i - 1];
        for (int g = pb + 1; g <= b; g++) g_start[g] = i;
    }
    if (i == NN - 1) {
        for (int g = b + 1; g <= GG; g++) g_start[g] = NN;
    }
}

// ---------------- merged: CSR fill (blocks < BF) + layer-0 GEMM (rest) -----------
__global__ void k_fill_gemm0(const int* __restrict__ ei,
                             const float* __restrict__ X, const float* __restrict__ W0) {
    GDC_WAIT();
    __shared__ float sW[FIN * HH];
    __shared__ float sx[16 * FIN];
    int t = threadIdx.x;
    if (blockIdx.x < BF) {
        int e = blockIdx.x * 256 + t;
        if (e < EE) {
            int s = ei[e];
            int d = ei[EE + e];
            int p = atomicAdd(&g_cur[d], 1);
            g_csr[p] = make_int2(s, __float_as_int(g_dinv[s] * g_dinv[d]));
        }
        return;
    }
    int rowBase = (blockIdx.x - BF) * 16;
    for (int idx = t; idx < FIN * HH; idx += 256) sW[idx] = W0[idx];
    if (t < 16 * FIN) {
        int r = rowBase + t / FIN;
        sx[t] = (r < NN) ? X[r * FIN + (t % FIN)] : 0.0f;
    }
    __syncthreads();
    int c = t & 127;
    int rh = t >> 7;
    float w[FIN];
    #pragma unroll
    for (int k = 0; k < FIN; k++) w[k] = sW[k * HH + c];
    #pragma unroll
    for (int i = 0; i < 8; i++) {
        int rloc = rh + 2 * i;
        int r = rowBase + rloc;
        if (r < NN) {
            float acc = 0.0f;
            #pragma unroll
            for (int k = 0; k < FIN; k++) acc += sx[rloc * FIN + k] * w[k];
            float other = __shfl_xor_sync(0xFFFFFFFF, acc, 1);
            if ((c & 1) == 0)
                g_hb[r * 64 + (c >> 1)] = packbf2(acc, other);
        }
    }
}

// ---------------- GEMM 128x128, single-term bf16: g_xb @ W -> g_hb --------------
__global__ void __launch_bounds__(256) k_gemm_tc(int layer) {
    GDC_WAIT();
    __shared__ unsigned sA[128][20];     // [row][k2] pitch 20
    __shared__ unsigned sB[16][136];     // [k2][n]  pitch 136
    int t = threadIdx.x;
    int rowBase = blockIdx.x * 128;
    int lane = t & 31, w = t >> 5;
    int wm = w >> 1, wn = w & 1;
    int gq = lane >> 2, cq = lane & 3;

    float acc[2][8][4];
    #pragma unroll
    for (int mt = 0; mt < 2; mt++)
        #pragma unroll
        for (int nt = 0; nt < 8; nt++)
            #pragma unroll
            for (int k = 0; k < 4; k++) acc[mt][nt][k] = 0.0f;

    const uint4* X4 = (const uint4*)g_xb;                      // [N][16] uint4
    const uint4* WH = (const uint4*)(g_wh + layer * 64 * HH);  // [64][32] uint4

    for (int kc = 0; kc < 4; kc++) {
        #pragma unroll
        for (int i = 0; i < 2; i++) {
            int idx = t + 256 * i;             // 0..511
            int r = idx >> 2, c4 = idx & 3;
            int gr = rowBase + r;
            uint4 v = (gr < NN) ? X4[gr * 16 + kc * 4 + c4]
                                : make_uint4(0u, 0u, 0u, 0u);
            *(uint4*)&sA[r][c4 * 4] = v;
        }
        #pragma unroll
        for (int i = 0; i < 2; i++) {
            int idx = t + 256 * i;             // 0..511
            int k2 = idx >> 5, n4 = idx & 31;  // k2 0..15
            *(uint4*)&sB[k2][n4 * 4] = WH[(kc * 16 + k2) * 32 + n4];
        }
        __syncthreads();

        #pragma unroll
        for (int ks = 0; ks < 2; ks++) {
            int kb2 = ks * 8;
            unsigned bh[8][2];
            #pragma unroll
            for (int nt = 0; nt < 8; nt++) {
                int n0 = wn * 64 + nt * 8 + gq;
                bh[nt][0] = sB[kb2 + cq][n0];
                bh[nt][1] = sB[kb2 + 4 + cq][n0];
            }
            unsigned ah[2][4];
            #pragma unroll
            for (int mt = 0; mt < 2; mt++) {
                int r0 = wm * 32 + mt * 16 + gq;
                ah[mt][0] = sA[r0][kb2 + cq];
                ah[mt][1] = sA[r0 + 8][kb2 + cq];
                ah[mt][2] = sA[r0][kb2 + 4 + cq];
                ah[mt][3] = sA[r0 + 8][kb2 + 4 + cq];
            }
            #pragma unroll
            for (int mt = 0; mt < 2; mt++)
                #pragma unroll
                for (int nt = 0; nt < 8; nt++)
                    mma_bf16(acc[mt][nt], ah[mt], bh[nt]);
        }
        __syncthreads();
    }

    #pragma unroll
    for (int mt = 0; mt < 2; mt++) {
        int r0 = rowBase + wm * 32 + mt * 16 + gq;
        #pragma unroll
        for (int nt = 0; nt < 8; nt++) {
            int col = wn * 64 + nt * 8 + cq * 2;
            if (r0 < NN)
                g_hb[r0 * 64 + (col >> 1)] = packbf2(acc[mt][nt][0], acc[mt][nt][1]);
            if (r0 + 8 < NN)
                g_hb[(r0 + 8) * 64 + (col >> 1)] = packbf2(acc[mt][nt][2], acc[mt][nt][3]);
        }
    }
}

// ---------------- aggregation: half-warp per node, uint4 gathers, 4x unroll ---------
__device__ __forceinline__ void bf8fma(float* acc, float w, uint4 p) {
    acc[0] += w * bflo(p.x);
    acc[1] += w * bfhi(p.x);
    acc[2] += w * bflo(p.y);
    acc[3] += w * bfhi(p.y);
    acc[4] += w * bflo(p.z);
    acc[5] += w * bfhi(p.z);
    acc[6] += w * bflo(p.w);
    acc[7] += w * bfhi(p.w);
}

__global__ void k_agg(const float* __restrict__ bvec,
                      const float* __restrict__ gamma, const float* __restrict__ beta,
                      const float* __restrict__ mean,  const float* __restrict__ var,
                      int residual) {
    GDC_WAIT();
    int idx = blockIdx.x * blockDim.x + threadIdx.x;
    int node = idx >> 4;
    if (node >= NN) return;
    int l16 = threadIdx.x & 15;
    const uint4* hb4 = (const uint4*)g_hb;   // [N][16] uint4
    uint4* xb4 = (uint4*)g_xb;

    float di = g_dinv[node];
    float self = di * di;
    float acc[8] = {0, 0, 0, 0, 0, 0, 0, 0};
    bf8fma(acc, self, hb4[node * 16 + l16]);

    int s0 = g_off[node], s1 = g_off[node + 1];
    int e = s0;
    for (; e + 4 <= s1; e += 4) {
        int2 sa = g_csr[e];
        int2 sb = g_csr[e + 1];
        int2 sc = g_csr[e + 2];
        int2 sd = g_csr[e + 3];
        uint4 pa = hb4[sa.x * 16 + l16];
        uint4 pb = hb4[sb.x * 16 + l16];
        uint4 pc = hb4[sc.x * 16 + l16];
        uint4 pd = hb4[sd.x * 16 + l16];
        bf8fma(acc, __int_as_float(sa.y), pa);
        bf8fma(acc, __int_as_float(sb.y), pb);
        bf8fma(acc, __int_as_float(sc.y), pc);
        bf8fma(acc, __int_as_float(sd.y), pd);
    }
    if (e + 2 <= s1) {
        int2 sa = g_csr[e];
        int2 sb = g_csr[e + 1];
        uint4 pa = hb4[sa.x * 16 + l16];
        uint4 pb = hb4[sb.x * 16 + l16];
        bf8fma(acc, __int_as_float(sa.y), pa);
        bf8fma(acc, __int_as_float(sb.y), pb);
        e += 2;
    }
    if (e < s1) {
        int2 se = g_csr[e];
        bf8fma(acc, __int_as_float(se.y), hb4[se.x * 16 + l16]);
    }

    int c0 = 8 * l16;
    float4 bv0 = *(const float4*)&bvec[c0],  bv1 = *(const float4*)&bvec[c0 + 4];
    float4 gm0 = *(const float4*)&gamma[c0], gm1 = *(const float4*)&gamma[c0 + 4];
    float4 bt0 = *(const float4*)&beta[c0],  bt1 = *(const float4*)&beta[c0 + 4];
    float4 mn0 = *(const float4*)&mean[c0],  mn1 = *(const float4*)&mean[c0 + 4];
    float4 vr0 = *(const float4*)&var[c0],   vr1 = *(const float4*)&var[c0 + 4];

    float b8[8]  = {bv0.x, bv0.y, bv0.z, bv0.w, bv1.x, bv1.y, bv1.z, bv1.w};
    float g8[8]  = {gm0.x, gm0.y, gm0.z, gm0.w, gm1.x, gm1.y, gm1.z, gm1.w};
    float t8[8]  = {bt0.x, bt0.y, bt0.z, bt0.w, bt1.x, bt1.y, bt1.z, bt1.w};
    float m8[8]  = {mn0.x, mn0.y, mn0.z, mn0.w, mn1.x, mn1.y, mn1.z, mn1.w};
    float v8[8]  = {vr0.x, vr0.y, vr0.z, vr0.w, vr1.x, vr1.y, vr1.z, vr1.w};

    float r8[8];
    #pragma unroll
    for (int j = 0; j < 8; j++) {
        float sc = g8[j] * rsqrtf(v8[j] + EPSV);
        r8[j] = fmaxf((acc[j] + b8[j] - m8[j]) * sc + t8[j], 0.0f);
    }

    if (residual) {
        uint4 xp = xb4[node * 16 + l16];
        r8[0] += bflo(xp.x); r8[1] += bfhi(xp.x);
        r8[2] += bflo(xp.y); r8[3] += bfhi(xp.y);
        r8[4] += bflo(xp.z); r8[5] += bfhi(xp.z);
        r8[6] += bflo(xp.w); r8[7] += bfhi(xp.w);
    }
    uint4 outw;
    outw.x = packbf2(r8[0], r8[1]);
    outw.y = packbf2(r8[2], r8[3]);
    outw.z = packbf2(r8[4], r8[5]);
    outw.w = packbf2(r8[6], r8[7]);
    xb4[node * 16 + l16] = outw;
}

// ---------------- fused pooling + MLP head (block per graph) ----------------
__global__ void k_pool_mlp(const float* __restrict__ l1w, const float* __restrict__ l1b,
                           const float* __restrict__ l2w, const float* __restrict__ l2b,
                           float* __restrict__ out) {
    GDC_WAIT();
    int g = blockIdx.x;
    int t = threadIdx.x;  // 128
    __shared__ float sp[HH];
    __shared__ float red[64];

    int s = g_start[g], e = g_start[g + 1];
    int wi = t >> 1, hi = t & 1;
    float sum = 0.0f;
    for (int r = s; r < e; r++) {
        unsigned w = g_xb[r * 64 + wi];
        sum += hi ? bfhi(w) : bflo(w);
    }
    float inv = 1.0f / fmaxf((float)(e - s), 1.0f);
    sp[t] = sum * inv;
    __syncthreads();

    if (t < 64) {
        float acc = l1b[t];
        #pragma unroll 8
        for (int k = 0; k < HH; k++) acc += sp[k] * l1w[k * 64 + t];
        float h1 = fmaxf(acc, 0.0f);
        red[t] = h1 * l2w[t];
    }
    __syncthreads();
    if (t < 32) {
        float v = red[t] + red[t + 32];
        #pragma unroll
        for (int d = 16; d > 0; d >>= 1) v += __shfl_down_sync(0xFFFFFFFF, v, d);
        if (t == 0) out[g] = v + l2b[0];
    }
}

// ---------------- PDL launch helper ----------------
template <typename F, typename... A>
static inline void pdl(F f, int grid, int block, A... args) {
    cudaLaunchConfig_t cfg = {};
    cfg.gridDim = dim3(grid, 1, 1);
    cfg.blockDim = dim3(block, 1, 1);
    cudaLaunchAttribute at[1];
    at[0].id = cudaLaunchAttributeProgrammaticStreamSerialization;
    at[0].val.programmaticStreamSerializationAllowed = 1;
    cfg.attrs = at;
    cfg.numAttrs = 1;
    cudaLaunchKernelEx(&cfg, f, args...);
}

// ---------------- launch ----------------
extern "C" void kernel_launch(void* const* d_in, const int* in_sizes, int n_in,
                              void* d_out, int out_size) {
    const float* x     = (const float*)d_in[0];
    const int*   ei    = (const int*)d_in[1];
    const int*   batch = (const int*)d_in[2];
    const float* W0    = (const float*)d_in[3];
    const float* b0    = (const float*)d_in[4];
    const float* Ws    = (const float*)d_in[5];
    const float* bs    = (const float*)d_in[6];
    const float* gam   = (const float*)d_in[7];
    const float* bet   = (const float*)d_in[8];
    const float* mean  = (const float*)d_in[9];
    const float* var   = (const float*)d_in[10];
    const float* l1w   = (const float*)d_in[11];
    const float* l1b   = (const float*)d_in[12];
    const float* l2w   = (const float*)d_in[13];
    const float* l2b   = (const float*)d_in[14];
    float* out = (float*)d_out;

    // graph prep
    pdl(k_zero_wpack, (NN + WSPL + 255) / 256, 256, Ws);
    pdl(k_count, (EE + 255) / 256, 256, ei);
    pdl(k_scan1, SCAN_B, 1024);
    pdl(k_scan3, (NN + 255) / 256, 256, batch);

    // CSR fill + layer-0 GEMM (merged)
    pdl(k_fill_gemm0, BF + (NN + 15) / 16, 256, ei, x, W0);
    pdl(k_agg, (NN * 16 + 255) / 256, 256, b0, gam, bet, mean, var, 0);

    // layers 1..4 (single-term bf16 tensor-core GEMM)
    for (int l = 1; l < LL; l++) {
        const float* b = bs + (l - 1) * HH;
        pdl(k_gemm_tc, (NN + 127) / 128, 256, l - 1);
        pdl(k_agg, (NN * 16 + 255) / 256, 256, b, gam + l * HH, bet + l * HH,
            mean + l * HH, var + l * HH, 1);
    }

    // fused pooling + head
    pdl(k_pool_mlp, GG, 128, l1w, l1b, l2w, l2b, out);
}